// round 15
// baseline (speedup 1.0000x reference)
#include <cuda_runtime.h>
#include <cuda_fp16.h>
#include <math.h>
#include <stdint.h>

#define DIMN     2048
#define NHEADS   16
#define HEAD_DIM 128
#define BATCH    2
#define SEQ      2048
#define MTOT     (BATCH*SEQ)   /* 4096 */

// ---------------- scratch (device globals; no runtime alloc allowed) --------
__device__ __half g_xh [(size_t)MTOT*DIMN];
__device__ __half g_wqh[(size_t)DIMN*DIMN];
__device__ __half g_wkh[(size_t)DIMN*DIMN];
__device__ __half g_wvh[(size_t)DIMN*DIMN];
__device__ __half g_woh[(size_t)DIMN*DIMN];
__device__ __half g_qh [(size_t)MTOT*DIMN];
__device__ __half g_kh [(size_t)MTOT*DIMN];
__device__ __half g_vt [(size_t)MTOT*DIMN];   // [b,h,d,s]
__device__ __half g_oh [(size_t)MTOT*DIMN];
__device__ __half g_mh [(size_t)SEQ*SEQ];     // fp16 mask

#define CP_ASYNC16(dst, src) \
    asm volatile("cp.async.cg.shared.global [%0], [%1], 16;\n" \
                 :: "r"(dst), "l"(src))
#define CP_COMMIT()  asm volatile("cp.async.commit_group;\n" ::)
#define CP_WAIT(n)   asm volatile("cp.async.wait_group %0;\n" :: "n"(n))

#define MMA_F16(acc, a0,a1,a2,a3, b0,b1)                                     \
    asm volatile(                                                            \
        "mma.sync.aligned.m16n8k16.row.col.f32.f16.f16.f32 "                 \
        "{%0,%1,%2,%3},{%4,%5,%6,%7},{%8,%9},{%0,%1,%2,%3};\n"               \
        : "+f"(acc[0]), "+f"(acc[1]), "+f"(acc[2]), "+f"(acc[3])             \
        : "r"(a0), "r"(a1), "r"(a2), "r"(a3), "r"(b0), "r"(b1))

// fp16-accumulate variant (2x rate): D/C are 2 regs = 4 halves
#define MMA_F16ACC(c0, c1, a0,a1,a2,a3, b0,b1)                               \
    asm volatile(                                                            \
        "mma.sync.aligned.m16n8k16.row.col.f16.f16.f16.f16 "                 \
        "{%0,%1},{%2,%3,%4,%5},{%6,%7},{%0,%1};\n"                           \
        : "+r"(c0), "+r"(c1)                                                 \
        : "r"(a0), "r"(a1), "r"(a2), "r"(a3), "r"(b0), "r"(b1))

#define LDSM_X4(r0, r1, r2, r3, gp)                                          \
    asm volatile("ldmatrix.sync.aligned.m8n8.x4.shared.b16 {%0,%1,%2,%3}, [%4];" \
        : "=r"(r0), "=r"(r1), "=r"(r2), "=r"(r3)                             \
        : "r"((unsigned)__cvta_generic_to_shared(gp)))

__device__ __forceinline__ unsigned pack_half2_rn(float a, float b) {
    half2 h = __float22half2_rn(make_float2(a, b));
    return *(unsigned*)&h;
}

// ---------------- merged fp32 -> fp16 rounding (x + weights + mask) ---------
#define NX4 (MTOT * DIMN / 4)
#define NW4 (DIMN * DIMN / 4)
#define NX8 (NX4 / 2)             /* 1M  */
#define NW8 (NW4 / 2)             /* 512K */
#define NM8 (SEQ * SEQ / 8)       /* 512K */

__global__ void round_all(const float* __restrict__ x,
                          const float* __restrict__ wq, const float* __restrict__ wk,
                          const float* __restrict__ wv, const float* __restrict__ wo,
                          const float* __restrict__ mask,
                          __half* __restrict__ xh,
                          __half* __restrict__ wqh, __half* __restrict__ wkh,
                          __half* __restrict__ wvh, __half* __restrict__ woh,
                          __half* __restrict__ mh)
{
    int i = blockIdx.x * blockDim.x + threadIdx.x;
    const float* in;
    __half* out;
    int j;
    if (i < NX8) {
        in = x; out = xh; j = i * 2;
    } else {
        int t = i - NX8;
        if (t < 4 * NW8) {
            int w = t >> 19;
            j = (t & (NW8 - 1)) * 2;
            in  = (w == 0) ? wq  : (w == 1) ? wk  : (w == 2) ? wv  : wo;
            out = (w == 0) ? wqh : (w == 1) ? wkh : (w == 2) ? wvh : woh;
        } else {
            int m = t - 4 * NW8;
            if (m >= NM8) return;
            in = mask; out = mh; j = m * 2;
        }
    }
    float4 v0 = ((const float4*)in)[j];
    float4 v1 = ((const float4*)in)[j + 1];
    ((half2*)out)[2 * j]     = __float22half2_rn(make_float2(v0.x, v0.y));
    ((half2*)out)[2 * j + 1] = __float22half2_rn(make_float2(v0.z, v0.w));
    ((half2*)out)[2 * j + 2] = __float22half2_rn(make_float2(v1.x, v1.y));
    ((half2*)out)[2 * j + 3] = __float22half2_rn(make_float2(v1.z, v1.w));
}

// ---------------- shared fp16 GEMM mainloop (3-stage, BK=64, 1 sync/iter) ---
#define HSTR 72      /* halfs per smem row: 64 + 8 pad (144B) */
#define GSTG 3
#define G_SMEM_BYTES (2 * GSTG * 128 * HSTR * 2)   /* 110592 */

__device__ __forceinline__ void gemm_mainloop(
    const __half* __restrict__ A, const __half* __restrict__ W,
    __half* As, __half* Bs, int m0, int n0, float acc[4][4][4])
{
    const int tid  = threadIdx.x;
    const int wid  = tid >> 5;
    const int lane = tid & 31;
    const int wm   = (wid & 1) * 64;
    const int wn   = (wid >> 1) * 32;

    const int a_off = (lane & 15) * HSTR + (lane >> 4) * 8;
    const int b_off = ((lane & 7) + (lane >> 4) * 8) * HSTR + ((lane >> 3) & 1) * 8;

    #define G_LOAD(st, k0) do {                                              \
        _Pragma("unroll")                                                    \
        for (int i = 0; i < 4; i++) {                                        \
            int idx = tid + i * 256;                                         \
            int row = idx >> 3;                                              \
            int c16 = idx & 7;                                               \
            unsigned da = (unsigned)__cvta_generic_to_shared(                \
                As + (st) * 128 * HSTR + row * HSTR + c16 * 8);              \
            CP_ASYNC16(da, (const void*)(A + (size_t)(m0 + row) * DIMN + (k0) + c16 * 8)); \
            unsigned db = (unsigned)__cvta_generic_to_shared(                \
                Bs + (st) * 128 * HSTR + row * HSTR + c16 * 8);              \
            CP_ASYNC16(db, (const void*)(W + (size_t)(n0 + row) * DIMN + (k0) + c16 * 8)); \
        }                                                                    \
        CP_COMMIT();                                                         \
    } while (0)

    const int NK = DIMN / 64;              // 32
    G_LOAD(0, 0);
    G_LOAD(1, 64);

    int cur = 0;
    for (int kt = 0; kt < NK; kt++) {
        CP_WAIT(1);
        __syncthreads();

        if (kt + 2 < NK) {
            int st2 = cur + 2; if (st2 >= GSTG) st2 -= GSTG;
            G_LOAD(st2, (kt + 2) * 64);
        }

        const __half* as = As + cur * 128 * HSTR + (size_t)wm * HSTR;
        const __half* bs = Bs + cur * 128 * HSTR + (size_t)wn * HSTR;

        #pragma unroll
        for (int ks = 0; ks < 4; ks++) {
            int kb = ks * 16;
            unsigned af[4][4], bf[4][2];
            #pragma unroll
            for (int mi = 0; mi < 4; mi++)
                LDSM_X4(af[mi][0], af[mi][1], af[mi][2], af[mi][3],
                        as + mi * 16 * HSTR + kb + a_off);
            #pragma unroll
            for (int njp = 0; njp < 2; njp++)
                LDSM_X4(bf[2*njp][0], bf[2*njp][1], bf[2*njp+1][0], bf[2*njp+1][1],
                        bs + njp * 16 * HSTR + kb + b_off);
            #pragma unroll
            for (int mi = 0; mi < 4; mi++)
                #pragma unroll
                for (int nj = 0; nj < 4; nj++)
                    MMA_F16(acc[mi][nj], af[mi][0], af[mi][1], af[mi][2], af[mi][3],
                            bf[nj][0], bf[nj][1]);
        }

        cur++; if (cur == GSTG) cur = 0;
    }
    #undef G_LOAD
}

// ---------------- QKV GEMM with fused RoPE / V-transpose epilogue -----------
extern __shared__ __half smg[];

__global__ __launch_bounds__(256, 2)
void gemm_qkv(const __half* __restrict__ xh,
              const __half* __restrict__ wqh, const __half* __restrict__ wkh,
              const __half* __restrict__ wvh,
              const float* __restrict__ fc, const float* __restrict__ fs,
              __half* __restrict__ qh, __half* __restrict__ kh,
              __half* __restrict__ vt)
{
    __half* As = smg;
    __half* Bs = smg + GSTG * 128 * HSTR;

    const int z = blockIdx.z;
    const __half* W = (z == 0) ? wqh : (z == 1 ? wkh : wvh);
    const int m0 = blockIdx.y * 128;
    const int n0 = blockIdx.x * 128;

    float acc[4][4][4];
    #pragma unroll
    for (int mi = 0; mi < 4; mi++)
        #pragma unroll
        for (int nj = 0; nj < 4; nj++)
            #pragma unroll
            for (int c = 0; c < 4; c++) acc[mi][nj][c] = 0.f;

    gemm_mainloop(xh, W, As, Bs, m0, n0, acc);

    const int tid  = threadIdx.x;
    const int wid  = tid >> 5;
    const int lane = tid & 31;
    const int lr   = lane >> 2;
    const int lc   = lane & 3;
    const int wm   = (wid & 1) * 64;
    const int wn   = (wid >> 1) * 32;
    const float SCALE = 0.08838834764831845f;

    if (z == 2) {
        #pragma unroll
        for (int mi = 0; mi < 4; mi++) {
            int r0 = m0 + wm + mi * 16 + lr;
            int b  = r0 >> 11;
            int s  = r0 & (SEQ - 1);
            #pragma unroll
            for (int nj = 0; nj < 4; nj++) {
                int cc = n0 + wn + nj * 8 + lc * 2;
                int h  = cc >> 7, d = cc & 127;
                size_t base = ((size_t)((b * NHEADS + h) * HEAD_DIM + d)) * SEQ;
                vt[base + s]           = __float2half_rn(acc[mi][nj][0]);
                vt[base + SEQ + s]     = __float2half_rn(acc[mi][nj][1]);
                vt[base + s + 8]       = __float2half_rn(acc[mi][nj][2]);
                vt[base + SEQ + s + 8] = __float2half_rn(acc[mi][nj][3]);
            }
        }
    } else {
        __half* dst = (z == 0) ? qh : kh;
        float sc = (z == 0) ? SCALE : 1.f;
        #pragma unroll
        for (int mi = 0; mi < 4; mi++) {
            int r0 = m0 + wm + mi * 16 + lr;
            int s1 = r0 & (SEQ - 1);
            #pragma unroll
            for (int nj = 0; nj < 4; nj++) {
                int cc = n0 + wn + nj * 8 + lc * 2;
                int fi = (cc & 127) >> 1;
                float c1 = fc[s1 * 64 + fi],       n1 = fs[s1 * 64 + fi];
                float c2 = fc[(s1 + 8) * 64 + fi], n2 = fs[(s1 + 8) * 64 + fi];
                float e1 = acc[mi][nj][0], o1 = acc[mi][nj][1];
                float e2 = acc[mi][nj][2], o2 = acc[mi][nj][3];
                *(half2*)&dst[(size_t)r0 * DIMN + cc] = __float22half2_rn(
                    make_float2((e1 * c1 - o1 * n1) * sc, (e1 * n1 + o1 * c1) * sc));
                *(half2*)&dst[(size_t)(r0 + 8) * DIMN + cc] = __float22half2_rn(
                    make_float2((e2 * c2 - o2 * n2) * sc, (e2 * n2 + o2 * c2) * sc));
            }
        }
    }
}

// ---------------- output projection GEMM (fp32 epilogue) --------------------
__global__ __launch_bounds__(256, 2)
void gemm_out(const __half* __restrict__ A, const __half* __restrict__ W,
              float* __restrict__ C)
{
    __half* As = smg;
    __half* Bs = smg + GSTG * 128 * HSTR;

    const int m0 = blockIdx.y * 128;
    const int n0 = blockIdx.x * 128;

    float acc[4][4][4];
    #pragma unroll
    for (int mi = 0; mi < 4; mi++)
        #pragma unroll
        for (int nj = 0; nj < 4; nj++)
            #pragma unroll
            for (int c = 0; c < 4; c++) acc[mi][nj][c] = 0.f;

    gemm_mainloop(A, W, As, Bs, m0, n0, acc);

    const int tid  = threadIdx.x;
    const int wid  = tid >> 5;
    const int lane = tid & 31;
    const int lr   = lane >> 2;
    const int lc   = lane & 3;
    const int wm   = (wid & 1) * 64;
    const int wn   = (wid >> 1) * 32;

    #pragma unroll
    for (int mi = 0; mi < 4; mi++) {
        int r0 = m0 + wm + mi * 16 + lr;
        #pragma unroll
        for (int nj = 0; nj < 4; nj++) {
            int cc = n0 + wn + nj * 8 + lc * 2;
            *(float2*)&C[(size_t)r0 * DIMN + cc] =
                make_float2(acc[mi][nj][0], acc[mi][nj][1]);
            *(float2*)&C[(size_t)(r0 + 8) * DIMN + cc] =
                make_float2(acc[mi][nj][2], acc[mi][nj][3]);
        }
    }
}

// ---------------- Flash attention: fp16-acc S, fp32-acc PV, 2 CTAs/SM -------
#define AQS 136
#define AKS 136
#define AVS 72

#define ATTN_SMEM_BYTES ((128*AQS + 2*64*AKS + 2*128*AVS) * 2)

__global__ __launch_bounds__(256, 2)
void attn_h(const __half* __restrict__ qh, const __half* __restrict__ kh,
            const __half* __restrict__ vt, const __half* __restrict__ maskh,
            __half* __restrict__ oh)
{
    extern __shared__ __half smh[];
    __half* Qs = smh;                       // [128][136]
    __half* Ks = Qs + 128 * AQS;            // [2][64][136]
    __half* Vs = Ks + 2 * 64 * AKS;         // [2][128][72]  (d-major)

    const int tid  = threadIdx.x;
    const int lane = tid & 31;
    const int w    = tid >> 5;
    const int lr   = lane >> 2;
    const int lc   = lane & 3;
    const int q0   = blockIdx.x * 128;
    const int h    = blockIdx.y;
    const int b    = blockIdx.z;
    const int bh   = b * NHEADS + h;

    const int aq_off = (lane & 15) * AQS + (lane >> 4) * 8;
    const int bk_off = ((lane & 7) + (lane >> 4) * 8) * AKS + ((lane >> 3) & 1) * 8;
    const int bv_off = ((lane & 7) + (lane >> 4) * 8) * AVS + ((lane >> 3) & 1) * 8;

    #define KV_LOAD(st, kv0) do {                                            \
        _Pragma("unroll")                                                    \
        for (int l = 0; l < 4; l++) {                                        \
            int idx = tid + l * 256;                                         \
            int rowk = idx >> 4;                                             \
            int ck   = idx & 15;                                             \
            unsigned dk = (unsigned)__cvta_generic_to_shared(                \
                Ks + (st) * 64 * AKS + rowk * AKS + ck * 8);                 \
            CP_ASYNC16(dk, (const void*)(kh + ((size_t)(b * SEQ + (kv0) + rowk)) * DIMN \
                                         + h * HEAD_DIM + ck * 8));          \
            int rowv = idx >> 3;                                             \
            int cv   = idx & 7;                                              \
            unsigned dv = (unsigned)__cvta_generic_to_shared(                \
                Vs + (st) * 128 * AVS + rowv * AVS + cv * 8);                \
            CP_ASYNC16(dv, (const void*)(vt + ((size_t)(bh * HEAD_DIM + rowv)) * SEQ \
                                         + (kv0) + cv * 8));                 \
        }                                                                    \
        CP_COMMIT();                                                         \
    } while (0)

    #pragma unroll
    for (int l = 0; l < 8; l++) {
        int idx = tid + l * 256;
        int row = idx >> 4;
        int c16 = idx & 15;
        unsigned dq = (unsigned)__cvta_generic_to_shared(Qs + row * AQS + c16 * 8);
        CP_ASYNC16(dq, (const void*)(qh + ((size_t)(b * SEQ + q0 + row)) * DIMN
                                     + h * HEAD_DIM + c16 * 8));
    }
    KV_LOAD(0, 0);

    CP_WAIT(0);
    __syncthreads();

    float o_acc[16][4];
    #pragma unroll
    for (int nt = 0; nt < 16; nt++)
        #pragma unroll
        for (int c = 0; c < 4; c++) o_acc[nt][c] = 0.f;
    float m_i[2] = {-1e30f, -1e30f};
    float l_i[2] = {0.f, 0.f};

    const int rA = w * 16 + lr;
    const int cb = lc * 2;
    const __half* qs_w = Qs + w * 16 * AQS + aq_off;

    const int NIT = SEQ / 64;                 // 32
    for (int it = 0; it < NIT; it++) {
        int st = it & 1;
        int kv0 = it * 64;
        if (it + 1 < NIT) KV_LOAD(st ^ 1, kv0 + 64);

        const __half* ks = Ks + st * 64 * AKS;
        const __half* vs = Vs + st * 128 * AVS;

        // ---- S = Q K^T with fp16 accumulation (2x mma rate) ----
        unsigned sh[8][2];
        #pragma unroll
        for (int nt = 0; nt < 8; nt++) { sh[nt][0] = 0u; sh[nt][1] = 0u; }

        #pragma unroll
        for (int kb = 0; kb < 8; kb++) {
            unsigned a0, a1, a2, a3;
            LDSM_X4(a0, a1, a2, a3, qs_w + kb * 16);
            #pragma unroll
            for (int ntp = 0; ntp < 4; ntp++) {
                unsigned b0, b1, b2, b3;
                LDSM_X4(b0, b1, b2, b3, ks + ntp * 16 * AKS + kb * 16 + bk_off);
                MMA_F16ACC(sh[2*ntp][0],   sh[2*ntp][1],   a0, a1, a2, a3, b0, b1);
                MMA_F16ACC(sh[2*ntp+1][0], sh[2*ntp+1][1], a0, a1, a2, a3, b2, b3);
            }
        }

        // unpack to fp32
        float s[8][4];
        #pragma unroll
        for (int nt = 0; nt < 8; nt++) {
            float2 f0 = __half22float2(*(half2*)&sh[nt][0]);
            float2 f1 = __half22float2(*(half2*)&sh[nt][1]);
            s[nt][0] = f0.x; s[nt][1] = f0.y;
            s[nt][2] = f1.x; s[nt][3] = f1.y;
        }

        // ---- + mask (fp16) ----
        #pragma unroll
        for (int nt = 0; nt < 8; nt++) {
            float2 mv0 = __half22float2(
                *(const half2*)&maskh[(size_t)(q0 + rA) * SEQ + kv0 + nt * 8 + cb]);
            float2 mv1 = __half22float2(
                *(const half2*)&maskh[(size_t)(q0 + rA + 8) * SEQ + kv0 + nt * 8 + cb]);
            s[nt][0] += mv0.x; s[nt][1] += mv0.y;
            s[nt][2] += mv1.x; s[nt][3] += mv1.y;
        }

        float mx0 = -1e30f, mx1 = -1e30f;
        #pragma unroll
        for (int nt = 0; nt < 8; nt++) {
            mx0 = fmaxf(mx0, fmaxf(s[nt][0], s[nt][1]));
            mx1 = fmaxf(mx1, fmaxf(s[nt][2], s[nt][3]));
        }
        #pragma unroll
        for (int o = 1; o < 4; o <<= 1) {
            mx0 = fmaxf(mx0, __shfl_xor_sync(0xffffffffu, mx0, o));
            mx1 = fmaxf(mx1, __shfl_xor_sync(0xffffffffu, mx1, o));
        }
        float mn0 = fmaxf(m_i[0], mx0);
        float mn1 = fmaxf(m_i[1], mx1);
        float al0 = __expf(m_i[0] - mn0);
        float al1 = __expf(m_i[1] - mn1);
        float rs0 = 0.f, rs1 = 0.f;
        #pragma unroll
        for (int nt = 0; nt < 8; nt++) {
            s[nt][0] = __expf(s[nt][0] - mn0);
            s[nt][1] = __expf(s[nt][1] - mn0);
            s[nt][2] = __expf(s[nt][2] - mn1);
            s[nt][3] = __expf(s[nt][3] - mn1);
            rs0 += s[nt][0] + s[nt][1];
            rs1 += s[nt][2] + s[nt][3];
        }
        #pragma unroll
        for (int o = 1; o < 4; o <<= 1) {
            rs0 += __shfl_xor_sync(0xffffffffu, rs0, o);
            rs1 += __shfl_xor_sync(0xffffffffu, rs1, o);
        }
        l_i[0] = l_i[0] * al0 + rs0;
        l_i[1] = l_i[1] * al1 + rs1;
        m_i[0] = mn0; m_i[1] = mn1;
        #pragma unroll
        for (int nt = 0; nt < 16; nt++) {
            o_acc[nt][0] *= al0; o_acc[nt][1] *= al0;
            o_acc[nt][2] *= al1; o_acc[nt][3] *= al1;
        }

        unsigned pa[4][4];
        #pragma unroll
        for (int kb = 0; kb < 4; kb++) {
            pa[kb][0] = pack_half2_rn(s[2*kb][0],   s[2*kb][1]);
            pa[kb][1] = pack_half2_rn(s[2*kb][2],   s[2*kb][3]);
            pa[kb][2] = pack_half2_rn(s[2*kb+1][0], s[2*kb+1][1]);
            pa[kb][3] = pack_half2_rn(s[2*kb+1][2], s[2*kb+1][3]);
        }

        #pragma unroll
        for (int kb = 0; kb < 4; kb++) {
            #pragma unroll
            for (int ntp = 0; ntp < 8; ntp++) {
                unsigned b0, b1, b2, b3;
                LDSM_X4(b0, b1, b2, b3, vs + ntp * 16 * AVS + kb * 16 + bv_off);
                MMA_F16(o_acc[2*ntp],   pa[kb][0], pa[kb][1], pa[kb][2], pa[kb][3], b0, b1);
                MMA_F16(o_acc[2*ntp+1], pa[kb][0], pa[kb][1], pa[kb][2], pa[kb][3], b2, b3);
            }
        }

        if (it + 1 < NIT) {
            CP_WAIT(0);
            __syncthreads();
        }
    }
    #undef KV_LOAD

    float inv0 = 1.f / l_i[0];
    float inv1 = 1.f / l_i[1];
    size_t orow0 = ((size_t)(b * SEQ + q0 + rA)) * DIMN + h * HEAD_DIM;
    size_t orow1 = ((size_t)(b * SEQ + q0 + rA + 8)) * DIMN + h * HEAD_DIM;
    #pragma unroll
    for (int nt = 0; nt < 16; nt++) {
        *(half2*)&oh[orow0 + nt * 8 + cb] =
            __float22half2_rn(make_float2(o_acc[nt][0] * inv0, o_acc[nt][1] * inv0));
        *(half2*)&oh[orow1 + nt * 8 + cb] =
            __float22half2_rn(make_float2(o_acc[nt][2] * inv1, o_acc[nt][3] * inv1));
    }
}

// ---------------- launcher ---------------------------------------------------
extern "C" void kernel_launch(void* const* d_in, const int* in_sizes, int n_in,
                              void* d_out, int out_size)
{
    const float* x    = (const float*)d_in[0];
    const float* fcos = (const float*)d_in[1];
    const float* fsin = (const float*)d_in[2];
    const float* mask = (const float*)d_in[3];
    const float* wq   = (const float*)d_in[4];
    const float* wk   = (const float*)d_in[5];
    const float* wv   = (const float*)d_in[6];
    const float* wo   = (const float*)d_in[7];
    float* out = (float*)d_out;

    __half *xh, *wqh, *wkh, *wvh, *woh, *qh, *kh, *vt, *oh, *mh;
    cudaGetSymbolAddress((void**)&xh,  g_xh);
    cudaGetSymbolAddress((void**)&wqh, g_wqh);
    cudaGetSymbolAddress((void**)&wkh, g_wkh);
    cudaGetSymbolAddress((void**)&wvh, g_wvh);
    cudaGetSymbolAddress((void**)&woh, g_woh);
    cudaGetSymbolAddress((void**)&qh,  g_qh);
    cudaGetSymbolAddress((void**)&kh,  g_kh);
    cudaGetSymbolAddress((void**)&vt,  g_vt);
    cudaGetSymbolAddress((void**)&oh,  g_oh);
    cudaGetSymbolAddress((void**)&mh,  g_mh);

    cudaFuncSetAttribute(gemm_qkv, cudaFuncAttributeMaxDynamicSharedMemorySize, G_SMEM_BYTES);
    cudaFuncSetAttribute(gemm_out, cudaFuncAttributeMaxDynamicSharedMemorySize, G_SMEM_BYTES);
    cudaFuncSetAttribute(attn_h, cudaFuncAttributeMaxDynamicSharedMemorySize,
                         ATTN_SMEM_BYTES);

    // 0. rn-round x + weights + mask to fp16 (single launch, 32B/thread)
    {
        int total = NX8 + 4 * NW8 + NM8;
        round_all<<<(total + 255) / 256, 256>>>(x, wq, wk, wv, wo, mask,
                                                xh, wqh, wkh, wvh, woh, mh);
    }

    // 1. fused QKV projections + RoPE + V transpose
    {
        dim3 grid(DIMN / 128, MTOT / 128, 3);   // (16, 32, 3)
        gemm_qkv<<<grid, 256, G_SMEM_BYTES>>>(xh, wqh, wkh, wvh, fcos, fsin, qh, kh, vt);
    }

    // 2. attention (fp16-acc S, 2 CTAs/SM, fp16 mask)
    {
        dim3 grid(SEQ / 128, NHEADS, BATCH);    // (16, 16, 2)
        attn_h<<<grid, 256, ATTN_SMEM_BYTES>>>(qh, kh, vt, mh, oh);
    }

    // 3. output projection -> d_out (fp32)
    {
        dim3 grid(DIMN / 128, MTOT / 128, 1);
        gemm_out<<<grid, 256, G_SMEM_BYTES>>>(oh, woh, out);
    }
}

// round 16
// speedup vs baseline: 1.0232x; 1.0232x over previous
#include <cuda_runtime.h>
#include <cuda_fp16.h>
#include <math.h>
#include <stdint.h>

#define DIMN     2048
#define NHEADS   16
#define HEAD_DIM 128
#define BATCH    2
#define SEQ      2048
#define MTOT     (BATCH*SEQ)   /* 4096 */

// ---------------- scratch (device globals; no runtime alloc allowed) --------
__device__ __half g_xh [(size_t)MTOT*DIMN];
__device__ __half g_wqh[(size_t)DIMN*DIMN];
__device__ __half g_wkh[(size_t)DIMN*DIMN];
__device__ __half g_wvh[(size_t)DIMN*DIMN];
__device__ __half g_woh[(size_t)DIMN*DIMN];
__device__ __half g_qh [(size_t)MTOT*DIMN];
__device__ __half g_kh [(size_t)MTOT*DIMN];
__device__ __half g_vt [(size_t)MTOT*DIMN];   // [b,h,d,s]
__device__ __half g_oh [(size_t)MTOT*DIMN];
__device__ __half g_mh [(size_t)SEQ*SEQ];     // fp16 mask

#define CP_ASYNC16(dst, src) \
    asm volatile("cp.async.cg.shared.global [%0], [%1], 16;\n" \
                 :: "r"(dst), "l"(src))
#define CP_COMMIT()  asm volatile("cp.async.commit_group;\n" ::)
#define CP_WAIT(n)   asm volatile("cp.async.wait_group %0;\n" :: "n"(n))

#define MMA_F16(acc, a0,a1,a2,a3, b0,b1)                                     \
    asm volatile(                                                            \
        "mma.sync.aligned.m16n8k16.row.col.f32.f16.f16.f32 "                 \
        "{%0,%1,%2,%3},{%4,%5,%6,%7},{%8,%9},{%0,%1,%2,%3};\n"               \
        : "+f"(acc[0]), "+f"(acc[1]), "+f"(acc[2]), "+f"(acc[3])             \
        : "r"(a0), "r"(a1), "r"(a2), "r"(a3), "r"(b0), "r"(b1))

#define LDSM_X4(r0, r1, r2, r3, gp)                                          \
    asm volatile("ldmatrix.sync.aligned.m8n8.x4.shared.b16 {%0,%1,%2,%3}, [%4];" \
        : "=r"(r0), "=r"(r1), "=r"(r2), "=r"(r3)                             \
        : "r"((unsigned)__cvta_generic_to_shared(gp)))

// packed fp16 2^x (approx) — produces the fp16 P fragment directly
#define EX2_F16X2(dst, src) \
    asm("ex2.approx.f16x2 %0, %1;" : "=r"(dst) : "r"(src))

__device__ __forceinline__ unsigned pack_half2_rn(float a, float b) {
    half2 h = __float22half2_rn(make_float2(a, b));
    return *(unsigned*)&h;
}

// ---------------- merged fp32 -> fp16 rounding (x + weights + mask) ---------
#define NX4 (MTOT * DIMN / 4)
#define NW4 (DIMN * DIMN / 4)
#define NX8 (NX4 / 2)             /* 1M  */
#define NW8 (NW4 / 2)             /* 512K */
#define NM8 (SEQ * SEQ / 8)       /* 512K */

__global__ void round_all(const float* __restrict__ x,
                          const float* __restrict__ wq, const float* __restrict__ wk,
                          const float* __restrict__ wv, const float* __restrict__ wo,
                          const float* __restrict__ mask,
                          __half* __restrict__ xh,
                          __half* __restrict__ wqh, __half* __restrict__ wkh,
                          __half* __restrict__ wvh, __half* __restrict__ woh,
                          __half* __restrict__ mh)
{
    int i = blockIdx.x * blockDim.x + threadIdx.x;
    const float* in;
    __half* out;
    int j;
    if (i < NX8) {
        in = x; out = xh; j = i * 2;
    } else {
        int t = i - NX8;
        if (t < 4 * NW8) {
            int w = t >> 19;
            j = (t & (NW8 - 1)) * 2;
            in  = (w == 0) ? wq  : (w == 1) ? wk  : (w == 2) ? wv  : wo;
            out = (w == 0) ? wqh : (w == 1) ? wkh : (w == 2) ? wvh : woh;
        } else {
            int m = t - 4 * NW8;
            if (m >= NM8) return;
            in = mask; out = mh; j = m * 2;
        }
    }
    float4 v0 = ((const float4*)in)[j];
    float4 v1 = ((const float4*)in)[j + 1];
    ((half2*)out)[2 * j]     = __float22half2_rn(make_float2(v0.x, v0.y));
    ((half2*)out)[2 * j + 1] = __float22half2_rn(make_float2(v0.z, v0.w));
    ((half2*)out)[2 * j + 2] = __float22half2_rn(make_float2(v1.x, v1.y));
    ((half2*)out)[2 * j + 3] = __float22half2_rn(make_float2(v1.z, v1.w));
}

// ---------------- shared fp16 GEMM mainloop (3-stage, BK=64, 1 sync/iter) ---
#define HSTR 72      /* halfs per smem row: 64 + 8 pad (144B) */
#define GSTG 3
#define G_SMEM_BYTES (2 * GSTG * 128 * HSTR * 2)   /* 110592 */

__device__ __forceinline__ void gemm_mainloop(
    const __half* __restrict__ A, const __half* __restrict__ W,
    __half* As, __half* Bs, int m0, int n0, float acc[4][4][4])
{
    const int tid  = threadIdx.x;
    const int wid  = tid >> 5;
    const int lane = tid & 31;
    const int wm   = (wid & 1) * 64;
    const int wn   = (wid >> 1) * 32;

    const int a_off = (lane & 15) * HSTR + (lane >> 4) * 8;
    const int b_off = ((lane & 7) + (lane >> 4) * 8) * HSTR + ((lane >> 3) & 1) * 8;

    #define G_LOAD(st, k0) do {                                              \
        _Pragma("unroll")                                                    \
        for (int i = 0; i < 4; i++) {                                        \
            int idx = tid + i * 256;                                         \
            int row = idx >> 3;                                              \
            int c16 = idx & 7;                                               \
            unsigned da = (unsigned)__cvta_generic_to_shared(                \
                As + (st) * 128 * HSTR + row * HSTR + c16 * 8);              \
            CP_ASYNC16(da, (const void*)(A + (size_t)(m0 + row) * DIMN + (k0) + c16 * 8)); \
            unsigned db = (unsigned)__cvta_generic_to_shared(                \
                Bs + (st) * 128 * HSTR + row * HSTR + c16 * 8);              \
            CP_ASYNC16(db, (const void*)(W + (size_t)(n0 + row) * DIMN + (k0) + c16 * 8)); \
        }                                                                    \
        CP_COMMIT();                                                         \
    } while (0)

    const int NK = DIMN / 64;              // 32
    G_LOAD(0, 0);
    G_LOAD(1, 64);

    int cur = 0;
    for (int kt = 0; kt < NK; kt++) {
        CP_WAIT(1);
        __syncthreads();

        if (kt + 2 < NK) {
            int st2 = cur + 2; if (st2 >= GSTG) st2 -= GSTG;
            G_LOAD(st2, (kt + 2) * 64);
        }

        const __half* as = As + cur * 128 * HSTR + (size_t)wm * HSTR;
        const __half* bs = Bs + cur * 128 * HSTR + (size_t)wn * HSTR;

        #pragma unroll
        for (int ks = 0; ks < 4; ks++) {
            int kb = ks * 16;
            unsigned af[4][4], bf[4][2];
            #pragma unroll
            for (int mi = 0; mi < 4; mi++)
                LDSM_X4(af[mi][0], af[mi][1], af[mi][2], af[mi][3],
                        as + mi * 16 * HSTR + kb + a_off);
            #pragma unroll
            for (int njp = 0; njp < 2; njp++)
                LDSM_X4(bf[2*njp][0], bf[2*njp][1], bf[2*njp+1][0], bf[2*njp+1][1],
                        bs + njp * 16 * HSTR + kb + b_off);
            #pragma unroll
            for (int mi = 0; mi < 4; mi++)
                #pragma unroll
                for (int nj = 0; nj < 4; nj++)
                    MMA_F16(acc[mi][nj], af[mi][0], af[mi][1], af[mi][2], af[mi][3],
                            bf[nj][0], bf[nj][1]);
        }

        cur++; if (cur == GSTG) cur = 0;
    }
    #undef G_LOAD
}

// ---------------- QKV GEMM with fused RoPE / V-transpose epilogue -----------
extern __shared__ __half smg[];

__global__ __launch_bounds__(256, 2)
void gemm_qkv(const __half* __restrict__ xh,
              const __half* __restrict__ wqh, const __half* __restrict__ wkh,
              const __half* __restrict__ wvh,
              const float* __restrict__ fc, const float* __restrict__ fs,
              __half* __restrict__ qh, __half* __restrict__ kh,
              __half* __restrict__ vt)
{
    __half* As = smg;
    __half* Bs = smg + GSTG * 128 * HSTR;

    const int z = blockIdx.z;
    const __half* W = (z == 0) ? wqh : (z == 1 ? wkh : wvh);
    const int m0 = blockIdx.y * 128;
    const int n0 = blockIdx.x * 128;

    float acc[4][4][4];
    #pragma unroll
    for (int mi = 0; mi < 4; mi++)
        #pragma unroll
        for (int nj = 0; nj < 4; nj++)
            #pragma unroll
            for (int c = 0; c < 4; c++) acc[mi][nj][c] = 0.f;

    gemm_mainloop(xh, W, As, Bs, m0, n0, acc);

    const int tid  = threadIdx.x;
    const int wid  = tid >> 5;
    const int lane = tid & 31;
    const int lr   = lane >> 2;
    const int lc   = lane & 3;
    const int wm   = (wid & 1) * 64;
    const int wn   = (wid >> 1) * 32;
    const float SCALE = 0.08838834764831845f;

    if (z == 2) {
        #pragma unroll
        for (int mi = 0; mi < 4; mi++) {
            int r0 = m0 + wm + mi * 16 + lr;
            int b  = r0 >> 11;
            int s  = r0 & (SEQ - 1);
            #pragma unroll
            for (int nj = 0; nj < 4; nj++) {
                int cc = n0 + wn + nj * 8 + lc * 2;
                int h  = cc >> 7, d = cc & 127;
                size_t base = ((size_t)((b * NHEADS + h) * HEAD_DIM + d)) * SEQ;
                vt[base + s]           = __float2half_rn(acc[mi][nj][0]);
                vt[base + SEQ + s]     = __float2half_rn(acc[mi][nj][1]);
                vt[base + s + 8]       = __float2half_rn(acc[mi][nj][2]);
                vt[base + SEQ + s + 8] = __float2half_rn(acc[mi][nj][3]);
            }
        }
    } else {
        __half* dst = (z == 0) ? qh : kh;
        float sc = (z == 0) ? SCALE : 1.f;
        #pragma unroll
        for (int mi = 0; mi < 4; mi++) {
            int r0 = m0 + wm + mi * 16 + lr;
            int s1 = r0 & (SEQ - 1);
            #pragma unroll
            for (int nj = 0; nj < 4; nj++) {
                int cc = n0 + wn + nj * 8 + lc * 2;
                int fi = (cc & 127) >> 1;
                float c1 = fc[s1 * 64 + fi],       n1 = fs[s1 * 64 + fi];
                float c2 = fc[(s1 + 8) * 64 + fi], n2 = fs[(s1 + 8) * 64 + fi];
                float e1 = acc[mi][nj][0], o1 = acc[mi][nj][1];
                float e2 = acc[mi][nj][2], o2 = acc[mi][nj][3];
                *(half2*)&dst[(size_t)r0 * DIMN + cc] = __float22half2_rn(
                    make_float2((e1 * c1 - o1 * n1) * sc, (e1 * n1 + o1 * c1) * sc));
                *(half2*)&dst[(size_t)(r0 + 8) * DIMN + cc] = __float22half2_rn(
                    make_float2((e2 * c2 - o2 * n2) * sc, (e2 * n2 + o2 * c2) * sc));
            }
        }
    }
}

// ---------------- output projection GEMM (fp32 epilogue) --------------------
__global__ __launch_bounds__(256, 2)
void gemm_out(const __half* __restrict__ A, const __half* __restrict__ W,
              float* __restrict__ C)
{
    __half* As = smg;
    __half* Bs = smg + GSTG * 128 * HSTR;

    const int m0 = blockIdx.y * 128;
    const int n0 = blockIdx.x * 128;

    float acc[4][4][4];
    #pragma unroll
    for (int mi = 0; mi < 4; mi++)
        #pragma unroll
        for (int nj = 0; nj < 4; nj++)
            #pragma unroll
            for (int c = 0; c < 4; c++) acc[mi][nj][c] = 0.f;

    gemm_mainloop(A, W, As, Bs, m0, n0, acc);

    const int tid  = threadIdx.x;
    const int wid  = tid >> 5;
    const int lane = tid & 31;
    const int lr   = lane >> 2;
    const int lc   = lane & 3;
    const int wm   = (wid & 1) * 64;
    const int wn   = (wid >> 1) * 32;

    #pragma unroll
    for (int mi = 0; mi < 4; mi++) {
        int r0 = m0 + wm + mi * 16 + lr;
        #pragma unroll
        for (int nj = 0; nj < 4; nj++) {
            int cc = n0 + wn + nj * 8 + lc * 2;
            *(float2*)&C[(size_t)r0 * DIMN + cc] =
                make_float2(acc[mi][nj][0], acc[mi][nj][1]);
            *(float2*)&C[(size_t)(r0 + 8) * DIMN + cc] =
                make_float2(acc[mi][nj][2], acc[mi][nj][3]);
        }
    }
}

// ---------------- Flash attention: fp32-acc S, f16x2 exp, 2 CTAs/SM ---------
#define AQS 136
#define AKS 136
#define AVS 72

#define ATTN_SMEM_BYTES ((128*AQS + 2*64*AKS + 2*128*AVS) * 2)

__global__ __launch_bounds__(256, 2)
void attn_h(const __half* __restrict__ qh, const __half* __restrict__ kh,
            const __half* __restrict__ vt, const __half* __restrict__ maskh,
            __half* __restrict__ oh)
{
    extern __shared__ __half smh[];
    __half* Qs = smh;                       // [128][136]
    __half* Ks = Qs + 128 * AQS;            // [2][64][136]
    __half* Vs = Ks + 2 * 64 * AKS;         // [2][128][72]  (d-major)

    const int tid  = threadIdx.x;
    const int lane = tid & 31;
    const int w    = tid >> 5;
    const int lr   = lane >> 2;
    const int lc   = lane & 3;
    const int q0   = blockIdx.x * 128;
    const int h    = blockIdx.y;
    const int b    = blockIdx.z;
    const int bh   = b * NHEADS + h;

    const int aq_off = (lane & 15) * AQS + (lane >> 4) * 8;
    const int bk_off = ((lane & 7) + (lane >> 4) * 8) * AKS + ((lane >> 3) & 1) * 8;
    const int bv_off = ((lane & 7) + (lane >> 4) * 8) * AVS + ((lane >> 3) & 1) * 8;

    #define KV_LOAD(st, kv0) do {                                            \
        _Pragma("unroll")                                                    \
        for (int l = 0; l < 4; l++) {                                        \
            int idx = tid + l * 256;                                         \
            int rowk = idx >> 4;                                             \
            int ck   = idx & 15;                                             \
            unsigned dk = (unsigned)__cvta_generic_to_shared(                \
                Ks + (st) * 64 * AKS + rowk * AKS + ck * 8);                 \
            CP_ASYNC16(dk, (const void*)(kh + ((size_t)(b * SEQ + (kv0) + rowk)) * DIMN \
                                         + h * HEAD_DIM + ck * 8));          \
            int rowv = idx >> 3;                                             \
            int cv   = idx & 7;                                              \
            unsigned dv = (unsigned)__cvta_generic_to_shared(                \
                Vs + (st) * 128 * AVS + rowv * AVS + cv * 8);                \
            CP_ASYNC16(dv, (const void*)(vt + ((size_t)(bh * HEAD_DIM + rowv)) * SEQ \
                                         + (kv0) + cv * 8));                 \
        }                                                                    \
        CP_COMMIT();                                                         \
    } while (0)

    #pragma unroll
    for (int l = 0; l < 8; l++) {
        int idx = tid + l * 256;
        int row = idx >> 4;
        int c16 = idx & 15;
        unsigned dq = (unsigned)__cvta_generic_to_shared(Qs + row * AQS + c16 * 8);
        CP_ASYNC16(dq, (const void*)(qh + ((size_t)(b * SEQ + q0 + row)) * DIMN
                                     + h * HEAD_DIM + c16 * 8));
    }
    KV_LOAD(0, 0);

    CP_WAIT(0);
    __syncthreads();

    float o_acc[16][4];
    #pragma unroll
    for (int nt = 0; nt < 16; nt++)
        #pragma unroll
        for (int c = 0; c < 4; c++) o_acc[nt][c] = 0.f;
    float m_i[2] = {-1e30f, -1e30f};
    float l_i[2] = {0.f, 0.f};

    const int rA = w * 16 + lr;
    const int cb = lc * 2;
    const __half* qs_w = Qs + w * 16 * AQS + aq_off;
    const half2 LOG2E = __float2half2_rn(1.4426950408889634f);

    const int NIT = SEQ / 64;                 // 32
    for (int it = 0; it < NIT; it++) {
        int st = it & 1;
        int kv0 = it * 64;
        if (it + 1 < NIT) KV_LOAD(st ^ 1, kv0 + 64);

        const __half* ks = Ks + st * 64 * AKS;
        const __half* vs = Vs + st * 128 * AVS;

        // ---- S = Q K^T (fp32 accumulation) ----
        float s[8][4];
        #pragma unroll
        for (int nt = 0; nt < 8; nt++)
            #pragma unroll
            for (int c = 0; c < 4; c++) s[nt][c] = 0.f;

        #pragma unroll
        for (int kb = 0; kb < 8; kb++) {
            unsigned a0, a1, a2, a3;
            LDSM_X4(a0, a1, a2, a3, qs_w + kb * 16);
            #pragma unroll
            for (int ntp = 0; ntp < 4; ntp++) {
                unsigned b0, b1, b2, b3;
                LDSM_X4(b0, b1, b2, b3, ks + ntp * 16 * AKS + kb * 16 + bk_off);
                MMA_F16(s[2*ntp],   a0, a1, a2, a3, b0, b1);
                MMA_F16(s[2*ntp+1], a0, a1, a2, a3, b2, b3);
            }
        }

        // ---- + mask (fp16) ----
        #pragma unroll
        for (int nt = 0; nt < 8; nt++) {
            float2 mv0 = __half22float2(
                *(const half2*)&maskh[(size_t)(q0 + rA) * SEQ + kv0 + nt * 8 + cb]);
            float2 mv1 = __half22float2(
                *(const half2*)&maskh[(size_t)(q0 + rA + 8) * SEQ + kv0 + nt * 8 + cb]);
            s[nt][0] += mv0.x; s[nt][1] += mv0.y;
            s[nt][2] += mv1.x; s[nt][3] += mv1.y;
        }

        // ---- online softmax: max + alpha in fp32 ----
        float mx0 = -1e30f, mx1 = -1e30f;
        #pragma unroll
        for (int nt = 0; nt < 8; nt++) {
            mx0 = fmaxf(mx0, fmaxf(s[nt][0], s[nt][1]));
            mx1 = fmaxf(mx1, fmaxf(s[nt][2], s[nt][3]));
        }
        #pragma unroll
        for (int o = 1; o < 4; o <<= 1) {
            mx0 = fmaxf(mx0, __shfl_xor_sync(0xffffffffu, mx0, o));
            mx1 = fmaxf(mx1, __shfl_xor_sync(0xffffffffu, mx1, o));
        }
        float mn0 = fmaxf(m_i[0], mx0);
        float mn1 = fmaxf(m_i[1], mx1);
        float al0 = __expf(m_i[0] - mn0);
        float al1 = __expf(m_i[1] - mn1);

        // ---- p = 2^((s-mn)*log2e) via ex2.approx.f16x2 -> fp16 fragments ----
        unsigned pa[4][4];
        float rs0 = 0.f, rs1 = 0.f;
        #pragma unroll
        for (int nt = 0; nt < 8; nt++) {
            half2 t01 = __floats2half2_rn(s[nt][0] - mn0, s[nt][1] - mn0);
            half2 t23 = __floats2half2_rn(s[nt][2] - mn1, s[nt][3] - mn1);
            t01 = __hmul2(t01, LOG2E);
            t23 = __hmul2(t23, LOG2E);
            unsigned p01, p23;
            EX2_F16X2(p01, *(unsigned*)&t01);
            EX2_F16X2(p23, *(unsigned*)&t23);
            pa[nt >> 1][(nt & 1) * 2]     = p01;
            pa[nt >> 1][(nt & 1) * 2 + 1] = p23;
            float2 f0 = __half22float2(*(half2*)&p01);
            float2 f1 = __half22float2(*(half2*)&p23);
            rs0 += f0.x + f0.y;
            rs1 += f1.x + f1.y;
        }
        #pragma unroll
        for (int o = 1; o < 4; o <<= 1) {
            rs0 += __shfl_xor_sync(0xffffffffu, rs0, o);
            rs1 += __shfl_xor_sync(0xffffffffu, rs1, o);
        }
        l_i[0] = l_i[0] * al0 + rs0;
        l_i[1] = l_i[1] * al1 + rs1;
        m_i[0] = mn0; m_i[1] = mn1;
        #pragma unroll
        for (int nt = 0; nt < 16; nt++) {
            o_acc[nt][0] *= al0; o_acc[nt][1] *= al0;
            o_acc[nt][2] *= al1; o_acc[nt][3] *= al1;
        }

        // ---- O += P V ----
        #pragma unroll
        for (int kb = 0; kb < 4; kb++) {
            #pragma unroll
            for (int ntp = 0; ntp < 8; ntp++) {
                unsigned b0, b1, b2, b3;
                LDSM_X4(b0, b1, b2, b3, vs + ntp * 16 * AVS + kb * 16 + bv_off);
                MMA_F16(o_acc[2*ntp],   pa[kb][0], pa[kb][1], pa[kb][2], pa[kb][3], b0, b1);
                MMA_F16(o_acc[2*ntp+1], pa[kb][0], pa[kb][1], pa[kb][2], pa[kb][3], b2, b3);
            }
        }

        if (it + 1 < NIT) {
            CP_WAIT(0);
            __syncthreads();
        }
    }
    #undef KV_LOAD

    float inv0 = 1.f / l_i[0];
    float inv1 = 1.f / l_i[1];
    size_t orow0 = ((size_t)(b * SEQ + q0 + rA)) * DIMN + h * HEAD_DIM;
    size_t orow1 = ((size_t)(b * SEQ + q0 + rA + 8)) * DIMN + h * HEAD_DIM;
    #pragma unroll
    for (int nt = 0; nt < 16; nt++) {
        *(half2*)&oh[orow0 + nt * 8 + cb] =
            __float22half2_rn(make_float2(o_acc[nt][0] * inv0, o_acc[nt][1] * inv0));
        *(half2*)&oh[orow1 + nt * 8 + cb] =
            __float22half2_rn(make_float2(o_acc[nt][2] * inv1, o_acc[nt][3] * inv1));
    }
}

// ---------------- launcher ---------------------------------------------------
extern "C" void kernel_launch(void* const* d_in, const int* in_sizes, int n_in,
                              void* d_out, int out_size)
{
    const float* x    = (const float*)d_in[0];
    const float* fcos = (const float*)d_in[1];
    const float* fsin = (const float*)d_in[2];
    const float* mask = (const float*)d_in[3];
    const float* wq   = (const float*)d_in[4];
    const float* wk   = (const float*)d_in[5];
    const float* wv   = (const float*)d_in[6];
    const float* wo   = (const float*)d_in[7];
    float* out = (float*)d_out;

    __half *xh, *wqh, *wkh, *wvh, *woh, *qh, *kh, *vt, *oh, *mh;
    cudaGetSymbolAddress((void**)&xh,  g_xh);
    cudaGetSymbolAddress((void**)&wqh, g_wqh);
    cudaGetSymbolAddress((void**)&wkh, g_wkh);
    cudaGetSymbolAddress((void**)&wvh, g_wvh);
    cudaGetSymbolAddress((void**)&woh, g_woh);
    cudaGetSymbolAddress((void**)&qh,  g_qh);
    cudaGetSymbolAddress((void**)&kh,  g_kh);
    cudaGetSymbolAddress((void**)&vt,  g_vt);
    cudaGetSymbolAddress((void**)&oh,  g_oh);
    cudaGetSymbolAddress((void**)&mh,  g_mh);

    cudaFuncSetAttribute(gemm_qkv, cudaFuncAttributeMaxDynamicSharedMemorySize, G_SMEM_BYTES);
    cudaFuncSetAttribute(gemm_out, cudaFuncAttributeMaxDynamicSharedMemorySize, G_SMEM_BYTES);
    cudaFuncSetAttribute(attn_h, cudaFuncAttributeMaxDynamicSharedMemorySize,
                         ATTN_SMEM_BYTES);

    // 0. rn-round x + weights + mask to fp16 (single launch, 32B/thread)
    {
        int total = NX8 + 4 * NW8 + NM8;
        round_all<<<(total + 255) / 256, 256>>>(x, wq, wk, wv, wo, mask,
                                                xh, wqh, wkh, wvh, woh, mh);
    }

    // 1. fused QKV projections + RoPE + V transpose
    {
        dim3 grid(DIMN / 128, MTOT / 128, 3);   // (16, 32, 3)
        gemm_qkv<<<grid, 256, G_SMEM_BYTES>>>(xh, wqh, wkh, wvh, fcos, fsin, qh, kh, vt);
    }

    // 2. attention (fp32-acc S, f16x2 exp, fp16 mask, 2 CTAs/SM)
    {
        dim3 grid(SEQ / 128, NHEADS, BATCH);    // (16, 16, 2)
        attn_h<<<grid, 256, ATTN_SMEM_BYTES>>>(qh, kh, vt, mh, oh);
    }

    // 3. output projection -> d_out (fp32)
    {
        dim3 grid(DIMN / 128, MTOT / 128, 1);
        gemm_out<<<grid, 256, G_SMEM_BYTES>>>(oh, woh, out);
    }
}

// round 17
// speedup vs baseline: 1.1054x; 1.0804x over previous
#include <cuda_runtime.h>
#include <cuda_fp16.h>
#include <math.h>
#include <stdint.h>

#define DIMN     2048
#define NHEADS   16
#define HEAD_DIM 128
#define BATCH    2
#define SEQ      2048
#define MTOT     (BATCH*SEQ)   /* 4096 */

// ---------------- scratch (device globals; no runtime alloc allowed) --------
__device__ __half g_xh [(size_t)MTOT*DIMN];
__device__ __half g_wqh[(size_t)DIMN*DIMN];
__device__ __half g_wkh[(size_t)DIMN*DIMN];
__device__ __half g_wvh[(size_t)DIMN*DIMN];
__device__ __half g_woh[(size_t)DIMN*DIMN];
__device__ __half g_qh [(size_t)MTOT*DIMN];
__device__ __half g_kh [(size_t)MTOT*DIMN];
__device__ __half g_vt [(size_t)MTOT*DIMN];   // [b,h,d,s]
__device__ __half g_oh [(size_t)MTOT*DIMN];
__device__ __half g_mh [(size_t)SEQ*SEQ];     // fp16 mask
__device__ int    g_mflag;                    // 1 iff mask has any nonzero

#define CP_ASYNC16(dst, src) \
    asm volatile("cp.async.cg.shared.global [%0], [%1], 16;\n" \
                 :: "r"(dst), "l"(src))
#define CP_COMMIT()  asm volatile("cp.async.commit_group;\n" ::)
#define CP_WAIT(n)   asm volatile("cp.async.wait_group %0;\n" :: "n"(n))

#define MMA_F16(acc, a0,a1,a2,a3, b0,b1)                                     \
    asm volatile(                                                            \
        "mma.sync.aligned.m16n8k16.row.col.f32.f16.f16.f32 "                 \
        "{%0,%1,%2,%3},{%4,%5,%6,%7},{%8,%9},{%0,%1,%2,%3};\n"               \
        : "+f"(acc[0]), "+f"(acc[1]), "+f"(acc[2]), "+f"(acc[3])             \
        : "r"(a0), "r"(a1), "r"(a2), "r"(a3), "r"(b0), "r"(b1))

#define LDSM_X4(r0, r1, r2, r3, gp)                                          \
    asm volatile("ldmatrix.sync.aligned.m8n8.x4.shared.b16 {%0,%1,%2,%3}, [%4];" \
        : "=r"(r0), "=r"(r1), "=r"(r2), "=r"(r3)                             \
        : "r"((unsigned)__cvta_generic_to_shared(gp)))

// packed fp16 2^x (approx) — produces the fp16 P fragment directly
#define EX2_F16X2(dst, src) \
    asm("ex2.approx.f16x2 %0, %1;" : "=r"(dst) : "r"(src))

__device__ __forceinline__ unsigned pack_half2_rn(float a, float b) {
    half2 h = __float22half2_rn(make_float2(a, b));
    return *(unsigned*)&h;
}

// ---------------- flag reset (graph-replay deterministic) -------------------
__global__ void zero_flag() { g_mflag = 0; }

// ---------------- merged fp32 -> fp16 rounding (x + weights + mask) ---------
#define NX4 (MTOT * DIMN / 4)
#define NW4 (DIMN * DIMN / 4)
#define NX8 (NX4 / 2)             /* 1M  */
#define NW8 (NW4 / 2)             /* 512K */
#define NM8 (SEQ * SEQ / 8)       /* 512K */

__global__ void round_all(const float* __restrict__ x,
                          const float* __restrict__ wq, const float* __restrict__ wk,
                          const float* __restrict__ wv, const float* __restrict__ wo,
                          const float* __restrict__ mask,
                          __half* __restrict__ xh,
                          __half* __restrict__ wqh, __half* __restrict__ wkh,
                          __half* __restrict__ wvh, __half* __restrict__ woh,
                          __half* __restrict__ mh)
{
    int i = blockIdx.x * blockDim.x + threadIdx.x;
    const float* in;
    __half* out;
    int j;
    bool is_mask = false;
    if (i < NX8) {
        in = x; out = xh; j = i * 2;
    } else {
        int t = i - NX8;
        if (t < 4 * NW8) {
            int w = t >> 19;
            j = (t & (NW8 - 1)) * 2;
            in  = (w == 0) ? wq  : (w == 1) ? wk  : (w == 2) ? wv  : wo;
            out = (w == 0) ? wqh : (w == 1) ? wkh : (w == 2) ? wvh : woh;
        } else {
            int m = t - 4 * NW8;
            if (m >= NM8) return;
            in = mask; out = mh; j = m * 2;
            is_mask = true;
        }
    }
    float4 v0 = ((const float4*)in)[j];
    float4 v1 = ((const float4*)in)[j + 1];
    if (is_mask) {
        bool nz = (v0.x != 0.f) | (v0.y != 0.f) | (v0.z != 0.f) | (v0.w != 0.f) |
                  (v1.x != 0.f) | (v1.y != 0.f) | (v1.z != 0.f) | (v1.w != 0.f);
        if (nz) atomicOr(&g_mflag, 1);
    }
    ((half2*)out)[2 * j]     = __float22half2_rn(make_float2(v0.x, v0.y));
    ((half2*)out)[2 * j + 1] = __float22half2_rn(make_float2(v0.z, v0.w));
    ((half2*)out)[2 * j + 2] = __float22half2_rn(make_float2(v1.x, v1.y));
    ((half2*)out)[2 * j + 3] = __float22half2_rn(make_float2(v1.z, v1.w));
}

// ---------------- shared fp16 GEMM mainloop (3-stage, BK=64, 1 sync/iter) ---
#define HSTR 72      /* halfs per smem row: 64 + 8 pad (144B) */
#define GSTG 3
#define G_SMEM_BYTES (2 * GSTG * 128 * HSTR * 2)   /* 110592 */

__device__ __forceinline__ void gemm_mainloop(
    const __half* __restrict__ A, const __half* __restrict__ W,
    __half* As, __half* Bs, int m0, int n0, float acc[4][4][4])
{
    const int tid  = threadIdx.x;
    const int wid  = tid >> 5;
    const int lane = tid & 31;
    const int wm   = (wid & 1) * 64;
    const int wn   = (wid >> 1) * 32;

    const int a_off = (lane & 15) * HSTR + (lane >> 4) * 8;
    const int b_off = ((lane & 7) + (lane >> 4) * 8) * HSTR + ((lane >> 3) & 1) * 8;

    #define G_LOAD(st, k0) do {                                              \
        _Pragma("unroll")                                                    \
        for (int i = 0; i < 4; i++) {                                        \
            int idx = tid + i * 256;                                         \
            int row = idx >> 3;                                              \
            int c16 = idx & 7;                                               \
            unsigned da = (unsigned)__cvta_generic_to_shared(                \
                As + (st) * 128 * HSTR + row * HSTR + c16 * 8);              \
            CP_ASYNC16(da, (const void*)(A + (size_t)(m0 + row) * DIMN + (k0) + c16 * 8)); \
            unsigned db = (unsigned)__cvta_generic_to_shared(                \
                Bs + (st) * 128 * HSTR + row * HSTR + c16 * 8);              \
            CP_ASYNC16(db, (const void*)(W + (size_t)(n0 + row) * DIMN + (k0) + c16 * 8)); \
        }                                                                    \
        CP_COMMIT();                                                         \
    } while (0)

    const int NK = DIMN / 64;              // 32
    G_LOAD(0, 0);
    G_LOAD(1, 64);

    int cur = 0;
    for (int kt = 0; kt < NK; kt++) {
        CP_WAIT(1);
        __syncthreads();

        if (kt + 2 < NK) {
            int st2 = cur + 2; if (st2 >= GSTG) st2 -= GSTG;
            G_LOAD(st2, (kt + 2) * 64);
        }

        const __half* as = As + cur * 128 * HSTR + (size_t)wm * HSTR;
        const __half* bs = Bs + cur * 128 * HSTR + (size_t)wn * HSTR;

        #pragma unroll
        for (int ks = 0; ks < 4; ks++) {
            int kb = ks * 16;
            unsigned af[4][4], bf[4][2];
            #pragma unroll
            for (int mi = 0; mi < 4; mi++)
                LDSM_X4(af[mi][0], af[mi][1], af[mi][2], af[mi][3],
                        as + mi * 16 * HSTR + kb + a_off);
            #pragma unroll
            for (int njp = 0; njp < 2; njp++)
                LDSM_X4(bf[2*njp][0], bf[2*njp][1], bf[2*njp+1][0], bf[2*njp+1][1],
                        bs + njp * 16 * HSTR + kb + b_off);
            #pragma unroll
            for (int mi = 0; mi < 4; mi++)
                #pragma unroll
                for (int nj = 0; nj < 4; nj++)
                    MMA_F16(acc[mi][nj], af[mi][0], af[mi][1], af[mi][2], af[mi][3],
                            bf[nj][0], bf[nj][1]);
        }

        cur++; if (cur == GSTG) cur = 0;
    }
    #undef G_LOAD
}

// ---------------- QKV GEMM with fused RoPE / V-transpose epilogue -----------
extern __shared__ __half smg[];

__global__ __launch_bounds__(256, 2)
void gemm_qkv(const __half* __restrict__ xh,
              const __half* __restrict__ wqh, const __half* __restrict__ wkh,
              const __half* __restrict__ wvh,
              const float* __restrict__ fc, const float* __restrict__ fs,
              __half* __restrict__ qh, __half* __restrict__ kh,
              __half* __restrict__ vt)
{
    __half* As = smg;
    __half* Bs = smg + GSTG * 128 * HSTR;

    const int z = blockIdx.z;
    const __half* W = (z == 0) ? wqh : (z == 1 ? wkh : wvh);
    const int m0 = blockIdx.y * 128;
    const int n0 = blockIdx.x * 128;

    float acc[4][4][4];
    #pragma unroll
    for (int mi = 0; mi < 4; mi++)
        #pragma unroll
        for (int nj = 0; nj < 4; nj++)
            #pragma unroll
            for (int c = 0; c < 4; c++) acc[mi][nj][c] = 0.f;

    gemm_mainloop(xh, W, As, Bs, m0, n0, acc);

    const int tid  = threadIdx.x;
    const int wid  = tid >> 5;
    const int lane = tid & 31;
    const int lr   = lane >> 2;
    const int lc   = lane & 3;
    const int wm   = (wid & 1) * 64;
    const int wn   = (wid >> 1) * 32;
    const float SCALE = 0.08838834764831845f;

    if (z == 2) {
        #pragma unroll
        for (int mi = 0; mi < 4; mi++) {
            int r0 = m0 + wm + mi * 16 + lr;
            int b  = r0 >> 11;
            int s  = r0 & (SEQ - 1);
            #pragma unroll
            for (int nj = 0; nj < 4; nj++) {
                int cc = n0 + wn + nj * 8 + lc * 2;
                int h  = cc >> 7, d = cc & 127;
                size_t base = ((size_t)((b * NHEADS + h) * HEAD_DIM + d)) * SEQ;
                vt[base + s]           = __float2half_rn(acc[mi][nj][0]);
                vt[base + SEQ + s]     = __float2half_rn(acc[mi][nj][1]);
                vt[base + s + 8]       = __float2half_rn(acc[mi][nj][2]);
                vt[base + SEQ + s + 8] = __float2half_rn(acc[mi][nj][3]);
            }
        }
    } else {
        __half* dst = (z == 0) ? qh : kh;
        float sc = (z == 0) ? SCALE : 1.f;
        #pragma unroll
        for (int mi = 0; mi < 4; mi++) {
            int r0 = m0 + wm + mi * 16 + lr;
            int s1 = r0 & (SEQ - 1);
            #pragma unroll
            for (int nj = 0; nj < 4; nj++) {
                int cc = n0 + wn + nj * 8 + lc * 2;
                int fi = (cc & 127) >> 1;
                float c1 = fc[s1 * 64 + fi],       n1 = fs[s1 * 64 + fi];
                float c2 = fc[(s1 + 8) * 64 + fi], n2 = fs[(s1 + 8) * 64 + fi];
                float e1 = acc[mi][nj][0], o1 = acc[mi][nj][1];
                float e2 = acc[mi][nj][2], o2 = acc[mi][nj][3];
                *(half2*)&dst[(size_t)r0 * DIMN + cc] = __float22half2_rn(
                    make_float2((e1 * c1 - o1 * n1) * sc, (e1 * n1 + o1 * c1) * sc));
                *(half2*)&dst[(size_t)(r0 + 8) * DIMN + cc] = __float22half2_rn(
                    make_float2((e2 * c2 - o2 * n2) * sc, (e2 * n2 + o2 * c2) * sc));
            }
        }
    }
}

// ---------------- output projection GEMM (fp32 epilogue) --------------------
__global__ __launch_bounds__(256, 2)
void gemm_out(const __half* __restrict__ A, const __half* __restrict__ W,
              float* __restrict__ C)
{
    __half* As = smg;
    __half* Bs = smg + GSTG * 128 * HSTR;

    const int m0 = blockIdx.y * 128;
    const int n0 = blockIdx.x * 128;

    float acc[4][4][4];
    #pragma unroll
    for (int mi = 0; mi < 4; mi++)
        #pragma unroll
        for (int nj = 0; nj < 4; nj++)
            #pragma unroll
            for (int c = 0; c < 4; c++) acc[mi][nj][c] = 0.f;

    gemm_mainloop(A, W, As, Bs, m0, n0, acc);

    const int tid  = threadIdx.x;
    const int wid  = tid >> 5;
    const int lane = tid & 31;
    const int lr   = lane >> 2;
    const int lc   = lane & 3;
    const int wm   = (wid & 1) * 64;
    const int wn   = (wid >> 1) * 32;

    #pragma unroll
    for (int mi = 0; mi < 4; mi++) {
        int r0 = m0 + wm + mi * 16 + lr;
        #pragma unroll
        for (int nj = 0; nj < 4; nj++) {
            int cc = n0 + wn + nj * 8 + lc * 2;
            *(float2*)&C[(size_t)r0 * DIMN + cc] =
                make_float2(acc[mi][nj][0], acc[mi][nj][1]);
            *(float2*)&C[(size_t)(r0 + 8) * DIMN + cc] =
                make_float2(acc[mi][nj][2], acc[mi][nj][3]);
        }
    }
}

// ---------------- Flash attention: fp32-acc S, f16x2 exp, skippable mask ----
#define AQS 136
#define AKS 136
#define AVS 72

#define ATTN_SMEM_BYTES ((128*AQS + 2*64*AKS + 2*128*AVS) * 2)

__global__ __launch_bounds__(256, 2)
void attn_h(const __half* __restrict__ qh, const __half* __restrict__ kh,
            const __half* __restrict__ vt, const __half* __restrict__ maskh,
            __half* __restrict__ oh)
{
    extern __shared__ __half smh[];
    __half* Qs = smh;                       // [128][136]
    __half* Ks = Qs + 128 * AQS;            // [2][64][136]
    __half* Vs = Ks + 2 * 64 * AKS;         // [2][128][72]  (d-major)

    const int tid  = threadIdx.x;
    const int lane = tid & 31;
    const int w    = tid >> 5;
    const int lr   = lane >> 2;
    const int lc   = lane & 3;
    const int q0   = blockIdx.x * 128;
    const int h    = blockIdx.y;
    const int b    = blockIdx.z;
    const int bh   = b * NHEADS + h;

    const int hasmask = g_mflag;            // uniform across grid

    const int aq_off = (lane & 15) * AQS + (lane >> 4) * 8;
    const int bk_off = ((lane & 7) + (lane >> 4) * 8) * AKS + ((lane >> 3) & 1) * 8;
    const int bv_off = ((lane & 7) + (lane >> 4) * 8) * AVS + ((lane >> 3) & 1) * 8;

    #define KV_LOAD(st, kv0) do {                                            \
        _Pragma("unroll")                                                    \
        for (int l = 0; l < 4; l++) {                                        \
            int idx = tid + l * 256;                                         \
            int rowk = idx >> 4;                                             \
            int ck   = idx & 15;                                             \
            unsigned dk = (unsigned)__cvta_generic_to_shared(                \
                Ks + (st) * 64 * AKS + rowk * AKS + ck * 8);                 \
            CP_ASYNC16(dk, (const void*)(kh + ((size_t)(b * SEQ + (kv0) + rowk)) * DIMN \
                                         + h * HEAD_DIM + ck * 8));          \
            int rowv = idx >> 3;                                             \
            int cv   = idx & 7;                                              \
            unsigned dv = (unsigned)__cvta_generic_to_shared(                \
                Vs + (st) * 128 * AVS + rowv * AVS + cv * 8);                \
            CP_ASYNC16(dv, (const void*)(vt + ((size_t)(bh * HEAD_DIM + rowv)) * SEQ \
                                         + (kv0) + cv * 8));                 \
        }                                                                    \
        CP_COMMIT();                                                         \
    } while (0)

    #pragma unroll
    for (int l = 0; l < 8; l++) {
        int idx = tid + l * 256;
        int row = idx >> 4;
        int c16 = idx & 15;
        unsigned dq = (unsigned)__cvta_generic_to_shared(Qs + row * AQS + c16 * 8);
        CP_ASYNC16(dq, (const void*)(qh + ((size_t)(b * SEQ + q0 + row)) * DIMN
                                     + h * HEAD_DIM + c16 * 8));
    }
    KV_LOAD(0, 0);

    CP_WAIT(0);
    __syncthreads();

    float o_acc[16][4];
    #pragma unroll
    for (int nt = 0; nt < 16; nt++)
        #pragma unroll
        for (int c = 0; c < 4; c++) o_acc[nt][c] = 0.f;
    float m_i[2] = {-1e30f, -1e30f};
    float l_i[2] = {0.f, 0.f};

    const int rA = w * 16 + lr;
    const int cb = lc * 2;
    const __half* qs_w = Qs + w * 16 * AQS + aq_off;
    const half2 LOG2E = __float2half2_rn(1.4426950408889634f);

    const int NIT = SEQ / 64;                 // 32
    for (int it = 0; it < NIT; it++) {
        int st = it & 1;
        int kv0 = it * 64;
        if (it + 1 < NIT) KV_LOAD(st ^ 1, kv0 + 64);

        const __half* ks = Ks + st * 64 * AKS;
        const __half* vs = Vs + st * 128 * AVS;

        // ---- S = Q K^T (fp32 accumulation) ----
        float s[8][4];
        #pragma unroll
        for (int nt = 0; nt < 8; nt++)
            #pragma unroll
            for (int c = 0; c < 4; c++) s[nt][c] = 0.f;

        #pragma unroll
        for (int kb = 0; kb < 8; kb++) {
            unsigned a0, a1, a2, a3;
            LDSM_X4(a0, a1, a2, a3, qs_w + kb * 16);
            #pragma unroll
            for (int ntp = 0; ntp < 4; ntp++) {
                unsigned b0, b1, b2, b3;
                LDSM_X4(b0, b1, b2, b3, ks + ntp * 16 * AKS + kb * 16 + bk_off);
                MMA_F16(s[2*ntp],   a0, a1, a2, a3, b0, b1);
                MMA_F16(s[2*ntp+1], a0, a1, a2, a3, b2, b3);
            }
        }

        // ---- + mask (fp16) — skipped entirely when the mask is all-zero ----
        if (hasmask) {
            #pragma unroll
            for (int nt = 0; nt < 8; nt++) {
                float2 mv0 = __half22float2(
                    *(const half2*)&maskh[(size_t)(q0 + rA) * SEQ + kv0 + nt * 8 + cb]);
                float2 mv1 = __half22float2(
                    *(const half2*)&maskh[(size_t)(q0 + rA + 8) * SEQ + kv0 + nt * 8 + cb]);
                s[nt][0] += mv0.x; s[nt][1] += mv0.y;
                s[nt][2] += mv1.x; s[nt][3] += mv1.y;
            }
        }

        // ---- online softmax: max + alpha in fp32 ----
        float mx0 = -1e30f, mx1 = -1e30f;
        #pragma unroll
        for (int nt = 0; nt < 8; nt++) {
            mx0 = fmaxf(mx0, fmaxf(s[nt][0], s[nt][1]));
            mx1 = fmaxf(mx1, fmaxf(s[nt][2], s[nt][3]));
        }
        #pragma unroll
        for (int o = 1; o < 4; o <<= 1) {
            mx0 = fmaxf(mx0, __shfl_xor_sync(0xffffffffu, mx0, o));
            mx1 = fmaxf(mx1, __shfl_xor_sync(0xffffffffu, mx1, o));
        }
        float mn0 = fmaxf(m_i[0], mx0);
        float mn1 = fmaxf(m_i[1], mx1);
        float al0 = __expf(m_i[0] - mn0);
        float al1 = __expf(m_i[1] - mn1);

        // ---- p = 2^((s-mn)*log2e) via ex2.approx.f16x2 -> fp16 fragments ----
        unsigned pa[4][4];
        float rs0 = 0.f, rs1 = 0.f;
        #pragma unroll
        for (int nt = 0; nt < 8; nt++) {
            half2 t01 = __floats2half2_rn(s[nt][0] - mn0, s[nt][1] - mn0);
            half2 t23 = __floats2half2_rn(s[nt][2] - mn1, s[nt][3] - mn1);
            t01 = __hmul2(t01, LOG2E);
            t23 = __hmul2(t23, LOG2E);
            unsigned p01, p23;
            EX2_F16X2(p01, *(unsigned*)&t01);
            EX2_F16X2(p23, *(unsigned*)&t23);
            pa[nt >> 1][(nt & 1) * 2]     = p01;
            pa[nt >> 1][(nt & 1) * 2 + 1] = p23;
            float2 f0 = __half22float2(*(half2*)&p01);
            float2 f1 = __half22float2(*(half2*)&p23);
            rs0 += f0.x + f0.y;
            rs1 += f1.x + f1.y;
        }
        #pragma unroll
        for (int o = 1; o < 4; o <<= 1) {
            rs0 += __shfl_xor_sync(0xffffffffu, rs0, o);
            rs1 += __shfl_xor_sync(0xffffffffu, rs1, o);
        }
        l_i[0] = l_i[0] * al0 + rs0;
        l_i[1] = l_i[1] * al1 + rs1;
        m_i[0] = mn0; m_i[1] = mn1;
        #pragma unroll
        for (int nt = 0; nt < 16; nt++) {
            o_acc[nt][0] *= al0; o_acc[nt][1] *= al0;
            o_acc[nt][2] *= al1; o_acc[nt][3] *= al1;
        }

        // ---- O += P V ----
        #pragma unroll
        for (int kb = 0; kb < 4; kb++) {
            #pragma unroll
            for (int ntp = 0; ntp < 8; ntp++) {
                unsigned b0, b1, b2, b3;
                LDSM_X4(b0, b1, b2, b3, vs + ntp * 16 * AVS + kb * 16 + bv_off);
                MMA_F16(o_acc[2*ntp],   pa[kb][0], pa[kb][1], pa[kb][2], pa[kb][3], b0, b1);
                MMA_F16(o_acc[2*ntp+1], pa[kb][0], pa[kb][1], pa[kb][2], pa[kb][3], b2, b3);
            }
        }

        if (it + 1 < NIT) {
            CP_WAIT(0);
            __syncthreads();
        }
    }
    #undef KV_LOAD

    float inv0 = 1.f / l_i[0];
    float inv1 = 1.f / l_i[1];
    size_t orow0 = ((size_t)(b * SEQ + q0 + rA)) * DIMN + h * HEAD_DIM;
    size_t orow1 = ((size_t)(b * SEQ + q0 + rA + 8)) * DIMN + h * HEAD_DIM;
    #pragma unroll
    for (int nt = 0; nt < 16; nt++) {
        *(half2*)&oh[orow0 + nt * 8 + cb] =
            __float22half2_rn(make_float2(o_acc[nt][0] * inv0, o_acc[nt][1] * inv0));
        *(half2*)&oh[orow1 + nt * 8 + cb] =
            __float22half2_rn(make_float2(o_acc[nt][2] * inv1, o_acc[nt][3] * inv1));
    }
}

// ---------------- launcher ---------------------------------------------------
extern "C" void kernel_launch(void* const* d_in, const int* in_sizes, int n_in,
                              void* d_out, int out_size)
{
    const float* x    = (const float*)d_in[0];
    const float* fcos = (const float*)d_in[1];
    const float* fsin = (const float*)d_in[2];
    const float* mask = (const float*)d_in[3];
    const float* wq   = (const float*)d_in[4];
    const float* wk   = (const float*)d_in[5];
    const float* wv   = (const float*)d_in[6];
    const float* wo   = (const float*)d_in[7];
    float* out = (float*)d_out;

    __half *xh, *wqh, *wkh, *wvh, *woh, *qh, *kh, *vt, *oh, *mh;
    cudaGetSymbolAddress((void**)&xh,  g_xh);
    cudaGetSymbolAddress((void**)&wqh, g_wqh);
    cudaGetSymbolAddress((void**)&wkh, g_wkh);
    cudaGetSymbolAddress((void**)&wvh, g_wvh);
    cudaGetSymbolAddress((void**)&woh, g_woh);
    cudaGetSymbolAddress((void**)&qh,  g_qh);
    cudaGetSymbolAddress((void**)&kh,  g_kh);
    cudaGetSymbolAddress((void**)&vt,  g_vt);
    cudaGetSymbolAddress((void**)&oh,  g_oh);
    cudaGetSymbolAddress((void**)&mh,  g_mh);

    cudaFuncSetAttribute(gemm_qkv, cudaFuncAttributeMaxDynamicSharedMemorySize, G_SMEM_BYTES);
    cudaFuncSetAttribute(gemm_out, cudaFuncAttributeMaxDynamicSharedMemorySize, G_SMEM_BYTES);
    cudaFuncSetAttribute(attn_h, cudaFuncAttributeMaxDynamicSharedMemorySize,
                         ATTN_SMEM_BYTES);

    // 0a. reset mask flag (graph-replay deterministic)
    zero_flag<<<1, 1>>>();

    // 0b. rn-round x + weights + mask to fp16; detect nonzero mask
    {
        int total = NX8 + 4 * NW8 + NM8;
        round_all<<<(total + 255) / 256, 256>>>(x, wq, wk, wv, wo, mask,
                                                xh, wqh, wkh, wvh, woh, mh);
    }

    // 1. fused QKV projections + RoPE + V transpose
    {
        dim3 grid(DIMN / 128, MTOT / 128, 3);   // (16, 32, 3)
        gemm_qkv<<<grid, 256, G_SMEM_BYTES>>>(xh, wqh, wkh, wvh, fcos, fsin, qh, kh, vt);
    }

    // 2. attention (fp32-acc S, f16x2 exp, mask skipped when all-zero)
    {
        dim3 grid(SEQ / 128, NHEADS, BATCH);    // (16, 16, 2)
        attn_h<<<grid, 256, ATTN_SMEM_BYTES>>>(qh, kh, vt, mh, oh);
    }

    // 3. output projection -> d_out (fp32)
    {
        dim3 grid(DIMN / 128, MTOT / 128, 1);
        gemm_out<<<grid, 256, G_SMEM_BYTES>>>(oh, woh, out);
    }
}